// round 11
// baseline (speedup 1.0000x reference)
#include <cuda_runtime.h>
#include <cstdint>

#define NL 7
#define BATCH 524288
#define TPB 256
#define GRID (BATCH / TPB)      // 2048
#define POSF (TPB * 3)          // floats per link in position staging = 768
#define POSB (POSF * 4)         // bytes per link pos region = 3072
#define QCHUNKS ((TPB * NL * 4) / 32)   // 32B chunks of q per block = 224

// 32-byte global load with L2 evict_last (ptxas requires v8.b32 width for this hint)
__device__ __forceinline__ void ldg32_evict_last(const void* p, uint32_t r[8]) {
    asm volatile("ld.global.nc.L2::evict_last.v8.b32 {%0,%1,%2,%3,%4,%5,%6,%7}, [%8];"
                 : "=r"(r[0]), "=r"(r[1]), "=r"(r[2]), "=r"(r[3]),
                   "=r"(r[4]), "=r"(r[5]), "=r"(r[6]), "=r"(r[7])
                 : "l"(p));
}

__device__ __forceinline__ void bulk_store_evict_first(void* gdst, const void* ssrc,
                                                       unsigned bytes) {
    uint64_t pol;
    asm volatile("createpolicy.fractional.L2::evict_first.b64 %0, 1.0;" : "=l"(pol));
    unsigned saddr = (unsigned)__cvta_generic_to_shared(ssrc);
    asm volatile(
        "cp.async.bulk.global.shared::cta.bulk_group.L2::cache_hint [%0], [%1], %2, %3;"
        :: "l"(gdst), "r"(saddr), "r"(bytes), "l"(pol) : "memory");
}

// One chain step for one pose. EXACT same fmaf expression tree as the known-good
// R2/R4 kernel (rel_err 2.3156e-4 deterministic) — do not reorder.
__device__ __forceinline__ void fk_step(int l, float qvl, float4 f,
                                        float vx, float vy, float vz,
                                        float& px, float& py, float& pz, float& pw,
                                        float& tx, float& ty, float& tz)
{
    // ---- translation update: t += rotate(p, tf) ----
    float c1x = fmaf(py, vz, -pz * vy);
    float c1y = fmaf(pz, vx, -px * vz);
    float c1z = fmaf(px, vy, -py * vx);
    float c2x = fmaf(pw, c1x, fmaf(py, c1z, -pz * c1y));
    float c2y = fmaf(pw, c1y, fmaf(pz, c1x, -px * c1z));
    float c2z = fmaf(pw, c1z, fmaf(px, c1y, -py * c1x));
    tx = fmaf(2.f, c2x, tx + vx);
    ty = fmaf(2.f, c2y, ty + vy);
    tz = fmaf(2.f, c2z, tz + vz);

    // ---- m = p (x) qf[l] ----
    float mw = fmaf(pw, f.w, -fmaf(px, f.x, fmaf(py, f.y, pz * f.z)));
    float mx = fmaf(pw, f.x, fmaf(px, f.w, fmaf(py, f.z, -pz * f.y)));
    float my = fmaf(pw, f.y, fmaf(-px, f.z, fmaf(py, f.w, pz * f.x)));
    float mz = fmaf(pw, f.z, fmaf(px, f.y, fmaf(-py, f.x, pz * f.w)));

    float s, c;
    __sincosf(0.5f * qvl, &s, &c);

    if ((l & 1) == 0) {
        // axis z: qa = (0,0,s,c)
        pw = fmaf(mw, c, -mz * s);
        px = fmaf(mx, c,  my * s);
        py = fmaf(my, c, -mx * s);
        pz = fmaf(mw, s,  mz * c);
    } else {
        // axis y: qa = (0,s,0,c)
        pw = fmaf(mw, c, -my * s);
        px = fmaf(mx, c, -mz * s);
        py = fmaf(mw, s,  my * c);
        pz = fmaf(mz, c,  mx * s);
    }
}

__global__ __launch_bounds__(TPB)
void fk_quat_kernel(const float* __restrict__ q,
                    const float* __restrict__ rot_fixed,
                    const float* __restrict__ trans_fixed,
                    float* __restrict__ out)
{
    __shared__ float4 sQF[NL];
    __shared__ float  sTF[NL * 3];
    // q staging (7KB) and position staging (21KB) used at different times
    __shared__ __align__(16) union SBuf {
        float q[TPB * NL];        // 1792 floats = 7168 B
        float pos[NL * POSF];     // 5376 floats
    } sB;

    const int tid  = threadIdx.x;
    const int base = blockIdx.x * TPB;

    // ---- cooperative coalesced q load, pinned in L2 (evict_last, 32B/lane) ----
    if (tid < QCHUNKS) {   // 224 threads
        uint32_t r[8];
        ldg32_evict_last((const char*)(q + (size_t)base * NL) + tid * 32, r);
        float4* sq4 = (float4*)((char*)sB.q + tid * 32);
        sq4[0] = make_float4(__uint_as_float(r[0]), __uint_as_float(r[1]),
                             __uint_as_float(r[2]), __uint_as_float(r[3]));
        sq4[1] = make_float4(__uint_as_float(r[4]), __uint_as_float(r[5]),
                             __uint_as_float(r[6]), __uint_as_float(r[7]));
    }

    // ---- fixed params -> quats/trans ----
    if (tid < NL) {
        const float* R = rot_fixed + tid * 9;
        float r00 = R[0], r01 = R[1], r02 = R[2];
        float r10 = R[3], r11 = R[4], r12 = R[5];
        float r20 = R[6], r21 = R[7], r22 = R[8];
        const float eps = 1e-9f;
        float qw = 0.5f * sqrtf(fmaxf(1.f + r00 + r11 + r22, eps));
        float qx = 0.5f * sqrtf(fmaxf(1.f + r00 - r11 - r22, eps));
        float qy = 0.5f * sqrtf(fmaxf(1.f - r00 + r11 - r22, eps));
        float qz = 0.5f * sqrtf(fmaxf(1.f - r00 - r11 + r22, eps));
        qx = copysignf(qx, r21 - r12);
        qy = copysignf(qy, r02 - r20);
        qz = copysignf(qz, r10 - r01);
        sQF[tid] = make_float4(qx, qy, qz, qw);
    }
    if (tid < NL * 3) sTF[tid] = trans_fixed[tid];
    __syncthreads();

    // ---- per-thread joint angles (stride-7 LDS, conflict-free) ----
    float qv[NL];
    #pragma unroll
    for (int i = 0; i < NL; i++) qv[i] = sB.q[tid * NL + i];
    __syncthreads();   // q buffer now reusable for position staging

    // Parent world pose: identity quaternion + zero translation
    float px = 0.f, py = 0.f, pz = 0.f, pw = 1.f;
    float tx = 0.f, ty = 0.f, tz = 0.f;

    const int b = base + tid;
    float4* qu_out = (float4*)(out + (size_t)NL * BATCH * 3);

    #pragma unroll
    for (int l = 0; l < NL; l++) {
        float4 f = sQF[l];
        float vx = sTF[l * 3 + 0], vy = sTF[l * 3 + 1], vz = sTF[l * 3 + 2];

        fk_step(l, qv[l], f, vx, vy, vz, px, py, pz, pw, tx, ty, tz);

        // ---- stage position (stride-3 STS, bank-conflict-free) ----
        float* p0 = &sB.pos[l * POSF + tid * 3];
        p0[0] = tx; p0[1] = ty; p0[2] = tz;

        // ---- canonical quaternion (w>=0), streaming float4 store ----
        float sgn = (pw < 0.f) ? -1.f : 1.f;
        __stcs(&qu_out[(size_t)l * BATCH + b],
               make_float4(sgn * px, sgn * py, sgn * pz, sgn * pw));
    }

    __syncthreads();

    // ---- flush positions via TMA bulk stores: 7 regions x 3072B, evict-first ----
    asm volatile("fence.proxy.async.shared::cta;" ::: "memory");
    if (tid < NL) {
        int l = tid;
        bulk_store_evict_first(out + ((size_t)l * BATCH + base) * 3,
                               &sB.pos[l * POSF], POSB);
        asm volatile("cp.async.bulk.commit_group;" ::: "memory");
        asm volatile("cp.async.bulk.wait_group 0;" ::: "memory");
    }
}

extern "C" void kernel_launch(void* const* d_in, const int* in_sizes, int n_in,
                              void* d_out, int out_size) {
    const float* q           = (const float*)d_in[0];
    const float* rot_fixed   = (const float*)d_in[1];
    const float* trans_fixed = (const float*)d_in[2];
    float* out = (float*)d_out;

    fk_quat_kernel<<<GRID, TPB>>>(q, rot_fixed, trans_fixed, out);
}

// round 12
// speedup vs baseline: 1.0202x; 1.0202x over previous
#include <cuda_runtime.h>
#include <cstdint>

#define NL 7
#define BATCH 524288
#define TPB 256
#define PPB (TPB * 2)           // poses per block = 512
#define GRID (BATCH / PPB)      // 1024
#define POSF (PPB * 3)          // floats per link in pos staging = 1536

typedef unsigned long long ull;

__device__ __forceinline__ ull f2pk(float lo, float hi) {
    ull r; asm("mov.b64 %0, {%1, %2};" : "=l"(r) : "f"(lo), "f"(hi)); return r;
}
__device__ __forceinline__ void f2upk(ull v, float& lo, float& hi) {
    asm("mov.b64 {%0, %1}, %2;" : "=f"(lo), "=f"(hi) : "l"(v));
}
__device__ __forceinline__ ull f2fma(ull a, ull b, ull c) {
    ull d; asm("fma.rn.f32x2 %0, %1, %2, %3;" : "=l"(d) : "l"(a), "l"(b), "l"(c)); return d;
}
__device__ __forceinline__ ull f2mul(ull a, ull b) {
    ull d; asm("mul.rn.f32x2 %0, %1, %2;" : "=l"(d) : "l"(a), "l"(b)); return d;
}
__device__ __forceinline__ ull f2add(ull a, ull b) {
    ull d; asm("add.rn.f32x2 %0, %1, %2;" : "=l"(d) : "l"(a), "l"(b)); return d;
}

__global__ __launch_bounds__(TPB, 4)
void fk_pk2_kernel(const float* __restrict__ q,
                   const float* __restrict__ rot_fixed,
                   const float* __restrict__ trans_fixed,
                   float* __restrict__ out)
{
    __shared__ ull sF[NL * 4];                       // fixed quat, packed broadcast
    __shared__ ull sV[NL * 3];                       // fixed trans, packed broadcast
    __shared__ __align__(16) float sQ[PPB * NL];     // joint angles, 14KB
    __shared__ __align__(16) float sPos[NL * POSF];  // position staging, 42KB

    const int tid  = threadIdx.x;
    const int base = blockIdx.x * PPB;

    // ---- cooperative coalesced q load: 896 float4 ----
    {
        const float4* gq4 = (const float4*)(q + (size_t)base * NL);
        float4* sq4 = (float4*)sQ;
        #pragma unroll
        for (int j = tid; j < (PPB * NL) / 4; j += TPB)
            sq4[j] = gq4[j];
    }

    // ---- fixed params -> packed broadcast (same values as frozen build) ----
    if (tid < NL) {
        const float* R = rot_fixed + tid * 9;
        float r00 = R[0], r01 = R[1], r02 = R[2];
        float r10 = R[3], r11 = R[4], r12 = R[5];
        float r20 = R[6], r21 = R[7], r22 = R[8];
        const float eps = 1e-9f;
        float qw = 0.5f * sqrtf(fmaxf(1.f + r00 + r11 + r22, eps));
        float qx = 0.5f * sqrtf(fmaxf(1.f + r00 - r11 - r22, eps));
        float qy = 0.5f * sqrtf(fmaxf(1.f - r00 + r11 - r22, eps));
        float qz = 0.5f * sqrtf(fmaxf(1.f - r00 - r11 + r22, eps));
        qx = copysignf(qx, r21 - r12);
        qy = copysignf(qy, r02 - r20);
        qz = copysignf(qz, r10 - r01);
        sF[tid * 4 + 0] = f2pk(qx, qx);
        sF[tid * 4 + 1] = f2pk(qy, qy);
        sF[tid * 4 + 2] = f2pk(qz, qz);
        sF[tid * 4 + 3] = f2pk(qw, qw);
        const float* tf = trans_fixed + tid * 3;
        sV[tid * 3 + 0] = f2pk(tf[0], tf[0]);
        sV[tid * 3 + 1] = f2pk(tf[1], tf[1]);
        sV[tid * 3 + 2] = f2pk(tf[2], tf[2]);
    }
    __syncthreads();

    const ull M1  = f2pk(-1.f, -1.f);
    const ull TWO = f2pk(2.f, 2.f);

    // packed state: pose A in lo lane, pose B (b+256) in hi lane
    ull PX = 0, PY = 0, PZ = 0, PW = f2pk(1.f, 1.f);
    ull TX = 0, TY = 0, TZ = 0;

    const int b0 = base + tid;
    const int b1 = b0 + TPB;
    float4* qu_out = (float4*)(out + (size_t)NL * BATCH * 3);

    #pragma unroll
    for (int l = 0; l < NL; l++) {
        // exact negation (rn(x * -1) == -x)
        ull NPX = f2mul(PX, M1);
        ull NPY = f2mul(PY, M1);
        ull NPZ = f2mul(PZ, M1);

        // ---- t += rotate(p, tf) — operand order matches frozen scalar tree ----
        {
            ull VX = sV[l * 3 + 0], VY = sV[l * 3 + 1], VZ = sV[l * 3 + 2];
            ull C1X = f2fma(PY, VZ, f2mul(NPZ, VY));
            ull C1Y = f2fma(PZ, VX, f2mul(NPX, VZ));
            ull C1Z = f2fma(PX, VY, f2mul(NPY, VX));
            ull C2X = f2fma(PW, C1X, f2fma(PY, C1Z, f2mul(NPZ, C1Y)));
            ull C2Y = f2fma(PW, C1Y, f2fma(PZ, C1X, f2mul(NPX, C1Z)));
            ull C2Z = f2fma(PW, C1Z, f2fma(PX, C1Y, f2mul(NPY, C1X)));
            TX = f2fma(TWO, C2X, f2add(TX, VX));
            TY = f2fma(TWO, C2Y, f2add(TY, VY));
            TZ = f2fma(TWO, C2Z, f2add(TZ, VZ));
        }

        // ---- m = p (x) qf[l]  (negation-propagated form == frozen tree) ----
        ull FX = sF[l * 4 + 0], FY = sF[l * 4 + 1], FZ = sF[l * 4 + 2], FW = sF[l * 4 + 3];
        ull MW = f2fma(PW, FW, f2fma(NPX, FX, f2fma(NPY, FY, f2mul(NPZ, FZ))));
        ull MX = f2fma(PW, FX, f2fma(PX,  FW, f2fma(PY,  FZ, f2mul(NPZ, FY))));
        ull MY = f2fma(PW, FY, f2fma(NPX, FZ, f2fma(PY,  FW, f2mul(PZ,  FX))));
        ull MZ = f2fma(PW, FZ, f2fma(PX,  FY, f2fma(NPY, FX, f2mul(PZ,  FW))));

        // ---- p = m (x) q_axis(half-angle) — EXACT frozen operand order ----
        {
            float a0 = sQ[tid * NL + l];
            float a1 = sQ[(tid + TPB) * NL + l];
            float s0, c0, s1, c1;
            __sincosf(0.5f * a0, &s0, &c0);
            __sincosf(0.5f * a1, &s1, &c1);
            ull S  = f2pk(s0, s1);
            ull C  = f2pk(c0, c1);
            ull NS = f2pk(-s0, -s1);

            if ((l & 1) == 0) {   // axis z
                // pw=fma(mw,c,-mz*s) px=fma(mx,c,my*s) py=fma(my,c,-mx*s) pz=fma(mw,s,mz*c)
                PW = f2fma(MW, C, f2mul(MZ, NS));
                PX = f2fma(MX, C, f2mul(MY, S));
                PY = f2fma(MY, C, f2mul(MX, NS));
                PZ = f2fma(MW, S, f2mul(MZ, C));   // order fixed vs R5
            } else {              // axis y
                // pw=fma(mw,c,-my*s) px=fma(mx,c,-mz*s) py=fma(mw,s,my*c) pz=fma(mz,c,mx*s)
                PW = f2fma(MW, C, f2mul(MY, NS));
                PX = f2fma(MX, C, f2mul(MZ, NS));
                PY = f2fma(MW, S, f2mul(MY, C));   // order fixed vs R5
                PZ = f2fma(MZ, C, f2mul(MX, S));
            }
        }

        // ---- stage positions (stride-3 STS, conflict-free) ----
        {
            float x0, x1, y0, y1, z0, z1;
            f2upk(TX, x0, x1); f2upk(TY, y0, y1); f2upk(TZ, z0, z1);
            float* p0 = &sPos[l * POSF + tid * 3];
            p0[0] = x0; p0[1] = y0; p0[2] = z0;
            float* p1 = &sPos[l * POSF + (tid + TPB) * 3];
            p1[0] = x1; p1[1] = y1; p1[2] = z1;
        }

        // ---- canonical quats (w>=0), streaming float4 stores ----
        {
            float x0, x1, y0, y1, z0, z1, w0, w1;
            f2upk(PX, x0, x1); f2upk(PY, y0, y1);
            f2upk(PZ, z0, z1); f2upk(PW, w0, w1);
            float g0 = (w0 < 0.f) ? -1.f : 1.f;
            float g1 = (w1 < 0.f) ? -1.f : 1.f;
            __stcs(&qu_out[(size_t)l * BATCH + b0],
                   make_float4(g0 * x0, g0 * y0, g0 * z0, g0 * w0));
            __stcs(&qu_out[(size_t)l * BATCH + b1],
                   make_float4(g1 * x1, g1 * y1, g1 * z1, g1 * w1));
        }
    }

    __syncthreads();

    // ---- flush positions: per link 384 float4 (2 coalesced sweeps), streaming ----
    const float4* sp4 = (const float4*)sPos;
    #pragma unroll
    for (int l = 0; l < NL; l++) {
        float4* gp4 = (float4*)(out + ((size_t)l * BATCH + base) * 3);
        __stcs(&gp4[tid],       sp4[l * (POSF / 4) + tid]);
        if (tid < POSF / 4 - TPB)   // 128 of 256 threads
            __stcs(&gp4[tid + TPB], sp4[l * (POSF / 4) + tid + TPB]);
    }
}

extern "C" void kernel_launch(void* const* d_in, const int* in_sizes, int n_in,
                              void* d_out, int out_size) {
    const float* q           = (const float*)d_in[0];
    const float* rot_fixed   = (const float*)d_in[1];
    const float* trans_fixed = (const float*)d_in[2];
    float* out = (float*)d_out;

    fk_pk2_kernel<<<GRID, TPB>>>(q, rot_fixed, trans_fixed, out);
}